// round 8
// baseline (speedup 1.0000x reference)
#include <cuda_runtime.h>
#include <math_constants.h>

#define BS   1024
#define DM   512
#define NH   8
#define DK   64
#define HIST 199
#define TT   200
#define TTILE 4
#define NTILES 50

// Scratch — referenced ONLY inside device code (host-side use passes the host
// shadow address; ATS makes it silently dereferenceable -> garbage).
__device__ float g_q[BS * DM];        // 2 MB
__device__ float g_r[BS * NH * DM];   // 16 MB
__device__ float g_c[BS * NH * DM];   // 16 MB

typedef unsigned long long u64;

// ---- packed f32x2 helpers --------------------------------------------------
__device__ __forceinline__ u64 pack2(float x, float y) {
    u64 r; asm("mov.b64 %0, {%1, %2};" : "=l"(r) : "f"(x), "f"(y)); return r;
}
__device__ __forceinline__ float2 unpack2(u64 v) {
    float2 d; asm("mov.b64 {%0, %1}, %2;" : "=f"(d.x), "=f"(d.y) : "l"(v)); return d;
}
__device__ __forceinline__ void ffma2(u64& acc, u64 a, u64 b) {
    asm("fma.rn.f32x2 %0, %1, %2, %0;" : "+l"(acc) : "l"(a), "l"(b));
}
__device__ __forceinline__ void fmul2(u64& a, u64 b) {
    asm("mul.rn.f32x2 %0, %0, %1;" : "+l"(a) : "l"(b));
}
// 16B read-only global load straight into two packed f32x2 regs
__device__ __forceinline__ void ldg16(const float* p, u64& a, u64& b) {
    asm volatile("ld.global.nc.v2.b64 {%0, %1}, [%2];" : "=l"(a), "=l"(b) : "l"(p));
}
__device__ __forceinline__ void pf2(const void* p) {
    asm volatile("prefetch.global.L2 [%0];" :: "l"(p));
}
__device__ __forceinline__ void cp16(void* smem_dst, const void* gsrc) {
    unsigned s = (unsigned)__cvta_generic_to_shared(smem_dst);
    asm volatile("cp.async.cg.shared.global [%0], [%1], 16;" :: "r"(s), "l"(gsrc));
}
__device__ __forceinline__ void cp_commit() { asm volatile("cp.async.commit_group;" ::: "memory"); }
__device__ __forceinline__ void cp_wait2()  { asm volatile("cp.async.wait_group 2;" ::: "memory"); }

// ============================================================================
// Kernel G: 16b x 64d NT GEMM, contiguous contraction K=512, grid (64, 8).
// QPROJ=true : g_q[b, y*64+d] = sum_k cur[b,k]            * B[(y*64+d)*512+k] + bias
// QPROJ=false: out[b, y*64+d] = sum_k g_c[b*4096+y*512+k] * B[(y*64+d)*512+k] + bias
// 3-stage cp.async pipeline, fma2 over k-pairs, XOR-swizzled smem.
// ============================================================================
__device__ __forceinline__ int swz(int cj, int row) { return 4 * (cj ^ ((row >> 1) & 7)); }

template<bool QPROJ>
__global__ void __launch_bounds__(256, 4) k_gemm64(
    const float* __restrict__ Aext, const float* __restrict__ B,
    const float* __restrict__ bias, float* __restrict__ outext)
{
    __shared__ __align__(16) float Cs[3][16][32];   // 6 KB
    __shared__ __align__(16) float Ws[3][64][32];   // 24 KB
    const int tid = threadIdx.x;
    const int bB = blockIdx.x * 16;
    const int y  = blockIdx.y;
    const float* Bb = B + (long)y * 64 * 512;
    const int d0 = (tid >> 4) * 4;        // 0..60
    const int b0 = tid & 15;              // 0..15

    const float* Abase = QPROJ ? Aext : (const float*)g_c;
    const long a_rstride = QPROJ ? 512 : 4096;
    const long a_yoff    = QPROJ ? 0   : (long)y * 512;

    u64 acc[4] = {0ull, 0ull, 0ull, 0ull};

    // chunk loaders
    const int la_row = tid >> 3, la_cj = tid & 7;           // A: first 128 threads
    #define LOAD_A(buf, kc) do { if (tid < 128) \
        cp16(&Cs[buf][la_row][swz(la_cj, la_row)], \
             Abase + (long)(bB + la_row) * a_rstride + a_yoff + (kc) * 32 + la_cj * 4); } while (0)
    #define LOAD_B(buf, kc) do { \
        _Pragma("unroll") for (int i = 0; i < 2; i++) { \
            int idx = tid + 256 * i; int d = idx >> 3, cj = idx & 7; \
            cp16(&Ws[buf][d][swz(cj, d)], Bb + (long)d * 512 + (kc) * 32 + cj * 4); } } while (0)

    LOAD_A(0, 0); LOAD_B(0, 0); cp_commit();
    LOAD_A(1, 1); LOAD_B(1, 1); cp_commit();

    for (int kc = 0; kc < 16; kc++) {
        const int buf = kc % 3;
        if (kc + 2 < 16) {
            const int nb = (kc + 2) % 3;
            LOAD_A(nb, kc + 2); LOAD_B(nb, kc + 2);
        }
        cp_commit();                       // uniform group count
        cp_wait2();                        // group kc complete
        __syncthreads();

#pragma unroll
        for (int jg = 0; jg < 8; jg++) {
            ulonglong2 wv[4];
#pragma unroll
            for (int dd = 0; dd < 4; dd++)
                wv[dd] = *(const ulonglong2*)&Ws[buf][d0 + dd][swz(jg, d0 + dd)];
            ulonglong2 cv = *(const ulonglong2*)&Cs[buf][b0][swz(jg, b0)];
#pragma unroll
            for (int dd = 0; dd < 4; dd++) {
                ffma2(acc[dd], cv.x, wv[dd].x);
                ffma2(acc[dd], cv.y, wv[dd].y);
            }
        }
        __syncthreads();                   // buf free for reuse next iter
    }

    float* Out = QPROJ ? (float*)g_q : outext;
    float4 bb = *(const float4*)&bias[y * 64 + d0];
    float v[4];
#pragma unroll
    for (int dd = 0; dd < 4; dd++) {
        float2 u = unpack2(acc[dd]);
        v[dd] = u.x + u.y;
    }
    float4 o = make_float4(v[0] + bb.x, v[1] + bb.y, v[2] + bb.z, v[3] + bb.w);
    *(float4*)&Out[(long)(bB + b0) * 512 + y * 64 + d0] = o;
}

// ============================================================================
// Kernel B: r[b,h,n] = sum_k q[b, h*64+k] * Wk[h*64+k, n]   (NN, K=64)
// ============================================================================
__global__ void __launch_bounds__(256) k_rproj(const float* __restrict__ Wk)
{
    __shared__ __align__(16) float Wks[64][128];
    __shared__ __align__(16) float qs[32][64];
    const int tid = threadIdx.x;
    const int nc = blockIdx.x;           // 0..3
    const int bB = blockIdx.y * 32;      // 0..31
    const int h  = blockIdx.z;           // 0..7

#pragma unroll
    for (int it = 0; it < 8; it++) {
        int idx = tid + 256 * it;
        int k = idx >> 5, n4 = (idx & 31) * 4;
        *(float4*)&Wks[k][n4] = *(const float4*)&Wk[(h * 64 + k) * 512 + nc * 128 + n4];
    }
#pragma unroll
    for (int it = 0; it < 2; it++) {
        int idx = tid + 256 * it;
        int bb = idx >> 4, k4 = (idx & 15) * 4;
        *(float4*)&qs[bb][k4] = *(const float4*)&g_q[(bB + bb) * 512 + h * 64 + k4];
    }
    __syncthreads();

    const int n0 = (tid & 31) * 4;
    const int b0 = (tid >> 5) * 4;
    u64 acc[4][2];
#pragma unroll
    for (int a = 0; a < 4; a++) { acc[a][0] = 0ull; acc[a][1] = 0ull; }

#pragma unroll
    for (int k = 0; k < 64; k++) {
        ulonglong2 w2 = *(const ulonglong2*)&Wks[k][n0];
#pragma unroll
        for (int cb = 0; cb < 4; cb++) {
            float x = qs[b0 + cb][k];
            u64 xx = pack2(x, x);
            ffma2(acc[cb][0], xx, w2.x);
            ffma2(acc[cb][1], xx, w2.y);
        }
    }
#pragma unroll
    for (int cb = 0; cb < 4; cb++) {
        float2 p0 = unpack2(acc[cb][0]), p1 = unpack2(acc[cb][1]);
        float4 o = make_float4(p0.x, p0.y, p1.x, p1.y);
        *(float4*)&g_r[((bB + b0 + cb) * 8 + h) * 512 + nc * 128 + n0] = o;
    }
}

// ============================================================================
// Kernel C: streaming attention via direct LDG + L1 reuse + L2 prefetch.
// 1 CTA / batch row, 256 thr. Warp w owns j-slice [w*64, w*64+64); lane
// (h = lane>>2, g = lane&3) owns floats w*64 + g*4 + {0..3,16..19,32..35,48..51}.
// x read twice per tile (scores, accumulate): 2nd read is an L1 hit.
// s_part double-buffered -> ONE __syncthreads per tile. No cp.async convoy.
// ============================================================================
__global__ void __launch_bounds__(256, 3) k_attn(
    const float* __restrict__ cur, const float* __restrict__ prev,
    const float* __restrict__ mask, const float* __restrict__ bk)
{
    __shared__ float s_part[2][8][8][TTILE];   // 2 KB
    __shared__ float mask_s[TT];
    __shared__ float sb_s[8];

    const int tid = threadIdx.x;
    const int b = blockIdx.x;
    const int w = tid >> 5, lane = tid & 31;
    const int h = lane >> 2, g = lane & 3;

    const float* prevb = prev + (long)b * HIST * 512;
    const float* curb  = cur  + (long)b * 512;

    if (tid < TT) mask_s[tid] = mask[b * TT + tid];
    {   // sb[h] = q[b,h,:]·bk[h,:]; warp w handles head w
        float q1 = g_q[b * 512 + w * 64 + lane];
        float q2 = g_q[b * 512 + w * 64 + 32 + lane];
        float s = q1 * bk[w * 64 + lane] + q2 * bk[w * 64 + 32 + lane];
#pragma unroll
        for (int o = 16; o; o >>= 1) s += __shfl_xor_sync(0xffffffffu, s, o);
        if (lane == 0) sb_s[w] = s;
    }

    // r fragment: 4 strided 16B chunks (matches x mapping)
    u64 rf[8];
    {
        const float* rp = &g_r[(long)b * 4096 + h * 512 + w * 64 + g * 4];
#pragma unroll
        for (int c = 0; c < 4; c++) ldg16(rp + 16 * c, rf[2 * c], rf[2 * c + 1]);
    }
    u64 acc[8];
#pragma unroll
    for (int i = 0; i < 8; i++) acc[i] = 0ull;
    float m = -CUDART_INF_F, l = 0.f;

    // L2 prime: tiles 0 and 1 (warp w covers row (w&3) of tile (w>>2))
    {
        int gt = (w >> 2) * TTILE + (w & 3);
        const float* src = (gt < HIST) ? prevb + (long)gt * 512 : curb;
        if (lane < 16) pf2(src + lane * 32);
    }
    __syncthreads();                       // sb_s / mask_s visible
    const float sb = sb_s[h];

    for (int tile = 0; tile < NTILES; tile++) {
        const int sbuf = tile & 1;

        // L2 prefetch 2 tiles ahead (warps 0-3, row w; 16 lanes x 128B = row)
        if (w < 4 && tile + 2 < NTILES) {
            int gt = (tile + 2) * TTILE + w;
            const float* src = (gt < HIST) ? prevb + (long)gt * 512 : curb;
            if (lane < 16) pf2(src + lane * 32);
        }

        // ---- partial scores ----
#pragma unroll
        for (int t = 0; t < TTILE; t++) {
            int gt = tile * TTILE + t;
            const float* xr = ((gt < HIST) ? prevb + (long)gt * 512 : curb)
                              + w * 64 + g * 4;
            u64 x0, x1, x2, x3, x4, x5, x6, x7;
            ldg16(xr,      x0, x1);
            ldg16(xr + 16, x2, x3);
            ldg16(xr + 32, x4, x5);
            ldg16(xr + 48, x6, x7);
            u64 sa = 0ull, sc = 0ull;
            ffma2(sa, rf[0], x0); ffma2(sc, rf[1], x1);
            ffma2(sa, rf[2], x2); ffma2(sc, rf[3], x3);
            ffma2(sa, rf[4], x4); ffma2(sc, rf[5], x5);
            ffma2(sa, rf[6], x6); ffma2(sc, rf[7], x7);
            float2 fa = unpack2(sa), fc = unpack2(sc);
            float s = (fa.x + fa.y) + (fc.x + fc.y);
            s += __shfl_xor_sync(0xffffffffu, s, 1);
            s += __shfl_xor_sync(0xffffffffu, s, 2);
            if (g == 0) s_part[sbuf][w][h][t] = s;
        }
        __syncthreads();                   // the ONLY barrier per tile

        // ---- per-lane replicated online softmax for head h ----
        float4 a0 = make_float4(0.f, 0.f, 0.f, 0.f);
#pragma unroll
        for (int w2 = 0; w2 < 8; w2++) {
            float4 v = *(const float4*)&s_part[sbuf][w2][h][0];
            a0.x += v.x; a0.y += v.y; a0.z += v.z; a0.w += v.w;
        }
        const float* mk = &mask_s[tile * TTILE];
        float lg0 = (a0.x + sb) * 0.125f + mk[0];
        float lg1 = (a0.y + sb) * 0.125f + mk[1];
        float lg2 = (a0.z + sb) * 0.125f + mk[2];
        float lg3 = (a0.w + sb) * 0.125f + mk[3];
        float mx = fmaxf(fmaxf(lg0, lg1), fmaxf(lg2, lg3));
        float m_new = fmaxf(m, mx);
        float p[TTILE];
        p[0] = __expf(lg0 - m_new); p[1] = __expf(lg1 - m_new);
        p[2] = __expf(lg2 - m_new); p[3] = __expf(lg3 - m_new);
        float ps = (p[0] + p[1]) + (p[2] + p[3]);
        float scl = __expf(m - m_new);
        l = l * scl + ps;
        m = m_new;

        // ---- rescale + accumulate weighted x (re-LDG: L1 hits) ----
        u64 sclp = pack2(scl, scl);
#pragma unroll
        for (int i = 0; i < 8; i++) fmul2(acc[i], sclp);
#pragma unroll
        for (int t = 0; t < TTILE; t++) {
            int gt = tile * TTILE + t;
            const float* xr = ((gt < HIST) ? prevb + (long)gt * 512 : curb)
                              + w * 64 + g * 4;
            u64 x0, x1, x2, x3, x4, x5, x6, x7;
            ldg16(xr,      x0, x1);
            ldg16(xr + 16, x2, x3);
            ldg16(xr + 32, x4, x5);
            ldg16(xr + 48, x6, x7);
            u64 pv = pack2(p[t], p[t]);
            ffma2(acc[0], pv, x0); ffma2(acc[1], pv, x1);
            ffma2(acc[2], pv, x2); ffma2(acc[3], pv, x3);
            ffma2(acc[4], pv, x4); ffma2(acc[5], pv, x5);
            ffma2(acc[6], pv, x6); ffma2(acc[7], pv, x7);
        }
        // no trailing barrier: s_part[sbuf] is rewritten only at tile+2,
        // which every warp reaches only after passing barrier(tile+1).
    }

    float inv = 1.0f / l;
    float* cpo = &g_c[((long)b * 8 + h) * 512 + w * 64 + g * 4];
#pragma unroll
    for (int c = 0; c < 4; c++) {
        float2 v0 = unpack2(acc[2 * c + 0]);
        float2 v1 = unpack2(acc[2 * c + 1]);
        float4 o = make_float4(v0.x * inv, v0.y * inv, v1.x * inv, v1.y * inv);
        *(float4*)(cpo + 16 * c) = o;
    }
}

// ============================================================================
extern "C" void kernel_launch(void* const* d_in, const int* in_sizes, int n_in,
                              void* d_out, int out_size)
{
    const float* cur  = (const float*)d_in[0];   // [1024, 512]
    const float* prev = (const float*)d_in[1];   // [1024, 199, 512]
    const float* mask = (const float*)d_in[2];   // [1024, 200]
    const float* Wq   = (const float*)d_in[3];   // [512, 512]
    const float* bq   = (const float*)d_in[4];   // [512]
    const float* Wk   = (const float*)d_in[5];   // [512, 512]
    const float* bk   = (const float*)d_in[6];   // [512]
    const float* Wv   = (const float*)d_in[7];   // [512, 512]
    const float* bv   = (const float*)d_in[8];   // [512]
    float* out = (float*)d_out;                  // [1024, 512]

    // q = cur @ Wq^T + bq          (writes g_q internally)
    k_gemm64<true ><<<dim3(64, 8), 256>>>(cur, Wq, bq, nullptr);
    // r[b,h,:] = Wk_h^T q_h        (g_q -> g_r)
    k_rproj<<<dim3(4, 32, 8), 256>>>(Wk);
    // streaming attention over raw embeddings (-> g_c)
    k_attn <<<dim3(1024), 256>>>(cur, prev, mask, bk);
    // out = c @ Wv_h^T + bv        (reads g_c internally)
    k_gemm64<false><<<dim3(64, 8), 256>>>(nullptr, Wv, bv, out);
}

// round 9
// speedup vs baseline: 1.3900x; 1.3900x over previous
#include <cuda_runtime.h>
#include <math_constants.h>

#define BS   1024
#define DM   512
#define NH   8
#define DK   64
#define HIST 199
#define TT   200
#define TTILE 4
#define NBUF 4
#define TSPLIT 4
#define T_PER_SPLIT 50
#define NT_SPLIT 13            // ceil(50/4)

// Scratch — referenced ONLY inside device code (host-side use passes the host
// shadow address; ATS makes it silently dereferenceable -> garbage).
__device__ float g_q[BS * DM];                     // 2 MB
__device__ float g_r[BS * NH * DM];                // 16 MB
__device__ float g_c[BS * NH * DM];                // 16 MB
__device__ float g_pc[BS * TSPLIT * NH * DM];      // 64 MB  unnormalized partial c
__device__ float g_pml[BS * TSPLIT * 16];          // 256 KB m[8], l[8] per (b,s)

typedef unsigned long long u64;

// ---- packed f32x2 helpers --------------------------------------------------
__device__ __forceinline__ u64 pack2(float x, float y) {
    u64 r; asm("mov.b64 %0, {%1, %2};" : "=l"(r) : "f"(x), "f"(y)); return r;
}
__device__ __forceinline__ float2 unpack2(u64 v) {
    float2 d; asm("mov.b64 {%0, %1}, %2;" : "=f"(d.x), "=f"(d.y) : "l"(v)); return d;
}
__device__ __forceinline__ void ffma2(u64& acc, u64 a, u64 b) {
    asm("fma.rn.f32x2 %0, %1, %2, %0;" : "+l"(acc) : "l"(a), "l"(b));
}
__device__ __forceinline__ void fmul2(u64& a, u64 b) {
    asm("mul.rn.f32x2 %0, %0, %1;" : "+l"(a) : "l"(b));
}
__device__ __forceinline__ void cp16(void* smem_dst, const void* gsrc) {
    unsigned s = (unsigned)__cvta_generic_to_shared(smem_dst);
    asm volatile("cp.async.cg.shared.global [%0], [%1], 16;" :: "r"(s), "l"(gsrc));
}
__device__ __forceinline__ void cp_commit() { asm volatile("cp.async.commit_group;" ::: "memory"); }
__device__ __forceinline__ void cp_wait2()  { asm volatile("cp.async.wait_group 2;" ::: "memory"); }
__device__ __forceinline__ void cp_wait1()  { asm volatile("cp.async.wait_group 1;" ::: "memory"); }

// ============================================================================
// Kernel G (R7 version — 24us measured): 32b x 64d NT GEMM, K=512, grid (32,8).
// QPROJ=true : g_q[b, y*64+d] = sum_k cur[b,k]            * B[(y*64+d)*512+k] + bias
// QPROJ=false: out[b, y*64+d] = sum_k g_c[b*4096+y*512+k] * B[(y*64+d)*512+k] + bias
// ============================================================================
__device__ __forceinline__ int swz(int cj, int row) { return 4 * (cj ^ ((row >> 1) & 7)); }

template<bool QPROJ>
__global__ void __launch_bounds__(256) k_gemm64(
    const float* __restrict__ Aext, const float* __restrict__ B,
    const float* __restrict__ bias, float* __restrict__ outext)
{
    __shared__ __align__(16) float Cs[2][32][32];   // 8 KB
    __shared__ __align__(16) float Ws[2][64][32];   // 16 KB
    const int tid = threadIdx.x;
    const int bB = blockIdx.x * 32;
    const int y  = blockIdx.y;
    const float* Bb = B + (long)y * 64 * 512;
    const int d0 = (tid >> 4) * 4;        // 0..60
    const int b0 = (tid & 15) * 2;        // 0..30

    const float* Abase = QPROJ ? Aext : (const float*)g_c;
    const long a_rstride = QPROJ ? 512 : 4096;
    const long a_yoff    = QPROJ ? 0   : (long)y * 512;

    u64 acc[2][4];
#pragma unroll
    for (int cb = 0; cb < 2; cb++)
#pragma unroll
        for (int dd = 0; dd < 4; dd++) acc[cb][dd] = 0ull;

    {
        int row = tid >> 3, cj = tid & 7;
        cp16(&Cs[0][row][swz(cj, row)],
             Abase + (long)(bB + row) * a_rstride + a_yoff + cj * 4);
    }
#pragma unroll
    for (int i = 0; i < 2; i++) {
        int idx = tid + 256 * i;
        int d = idx >> 3, cj = idx & 7;
        cp16(&Ws[0][d][swz(cj, d)], Bb + (long)d * 512 + cj * 4);
    }
    cp_commit();

    for (int kc = 0; kc < 16; kc++) {
        const int buf = kc & 1;
        if (kc + 1 < 16) {
            {
                int row = tid >> 3, cj = tid & 7;
                cp16(&Cs[buf ^ 1][row][swz(cj, row)],
                     Abase + (long)(bB + row) * a_rstride + a_yoff + (kc + 1) * 32 + cj * 4);
            }
#pragma unroll
            for (int i = 0; i < 2; i++) {
                int idx = tid + 256 * i;
                int d = idx >> 3, cj = idx & 7;
                cp16(&Ws[buf ^ 1][d][swz(cj, d)],
                     Bb + (long)d * 512 + (kc + 1) * 32 + cj * 4);
            }
        }
        cp_commit();
        cp_wait1();
        __syncthreads();

#pragma unroll
        for (int jg = 0; jg < 8; jg++) {
            ulonglong2 wv[4], cv[2];
#pragma unroll
            for (int dd = 0; dd < 4; dd++)
                wv[dd] = *(const ulonglong2*)&Ws[buf][d0 + dd][swz(jg, d0 + dd)];
#pragma unroll
            for (int cb = 0; cb < 2; cb++)
                cv[cb] = *(const ulonglong2*)&Cs[buf][b0 + cb][swz(jg, b0 + cb)];
#pragma unroll
            for (int cb = 0; cb < 2; cb++)
#pragma unroll
                for (int dd = 0; dd < 4; dd++) {
                    ffma2(acc[cb][dd], cv[cb].x, wv[dd].x);
                    ffma2(acc[cb][dd], cv[cb].y, wv[dd].y);
                }
        }
        __syncthreads();
    }

    float* Out = QPROJ ? (float*)g_q : outext;
    float4 bb = *(const float4*)&bias[y * 64 + d0];
#pragma unroll
    for (int cb = 0; cb < 2; cb++) {
        float v[4];
#pragma unroll
        for (int dd = 0; dd < 4; dd++) {
            float2 u = unpack2(acc[cb][dd]);
            v[dd] = u.x + u.y;
        }
        float4 o = make_float4(v[0] + bb.x, v[1] + bb.y, v[2] + bb.z, v[3] + bb.w);
        *(float4*)&Out[(long)(bB + b0 + cb) * 512 + y * 64 + d0] = o;
    }
}

// ============================================================================
// Kernel B: r[b,h,n] = sum_k q[b, h*64+k] * Wk[h*64+k, n]   (NN, K=64)
// ============================================================================
__global__ void __launch_bounds__(256) k_rproj(const float* __restrict__ Wk)
{
    __shared__ __align__(16) float Wks[64][128];
    __shared__ __align__(16) float qs[32][64];
    const int tid = threadIdx.x;
    const int nc = blockIdx.x;
    const int bB = blockIdx.y * 32;
    const int h  = blockIdx.z;

#pragma unroll
    for (int it = 0; it < 8; it++) {
        int idx = tid + 256 * it;
        int k = idx >> 5, n4 = (idx & 31) * 4;
        *(float4*)&Wks[k][n4] = *(const float4*)&Wk[(h * 64 + k) * 512 + nc * 128 + n4];
    }
#pragma unroll
    for (int it = 0; it < 2; it++) {
        int idx = tid + 256 * it;
        int bb = idx >> 4, k4 = (idx & 15) * 4;
        *(float4*)&qs[bb][k4] = *(const float4*)&g_q[(bB + bb) * 512 + h * 64 + k4];
    }
    __syncthreads();

    const int n0 = (tid & 31) * 4;
    const int b0 = (tid >> 5) * 4;
    u64 acc[4][2];
#pragma unroll
    for (int a = 0; a < 4; a++) { acc[a][0] = 0ull; acc[a][1] = 0ull; }

#pragma unroll
    for (int k = 0; k < 64; k++) {
        ulonglong2 w2 = *(const ulonglong2*)&Wks[k][n0];
#pragma unroll
        for (int cb = 0; cb < 4; cb++) {
            float x = qs[b0 + cb][k];
            u64 xx = pack2(x, x);
            ffma2(acc[cb][0], xx, w2.x);
            ffma2(acc[cb][1], xx, w2.y);
        }
    }
#pragma unroll
    for (int cb = 0; cb < 4; cb++) {
        float2 p0 = unpack2(acc[cb][0]), p1 = unpack2(acc[cb][1]);
        float4 o = make_float4(p0.x, p0.y, p1.x, p1.y);
        *(float4*)&g_r[((bB + b0 + cb) * 8 + h) * 512 + nc * 128 + n0] = o;
    }
}

// ============================================================================
// Kernel C: SPLIT-T streaming attention (R7 internals, 4-way T split).
// grid (1024, 4): CTA (b,s) handles timesteps [s*50, s*50+50), 13 tiles of 4.
// Writes UNNORMALIZED partial acc to g_pc and (m, l) to g_pml.
// ============================================================================
__device__ __forceinline__ void prefetch_tile_s(
    float* dst, const float* __restrict__ prevb, const float* __restrict__ curb,
    int s, int tile, int tid)
{
#pragma unroll
    for (int i = 0; i < 2; i++) {
        int idx = tid + 256 * i;        // 512 float4 = 4 rows x 512 floats
        int tr = idx >> 7;
        int c = (idx & 127) * 4;
        int lt = tile * TTILE + tr;     // 0..51
        if (lt > T_PER_SPLIT - 1) lt = T_PER_SPLIT - 1;   // clamp (masked -inf)
        int gt = s * T_PER_SPLIT + lt;  // <= 199
        const float* src = (gt < HIST) ? (prevb + (long)gt * 512 + c) : (curb + c);
        cp16(dst + tr * 512 + c, src);
    }
}

__global__ void __launch_bounds__(256) k_attn(
    const float* __restrict__ cur, const float* __restrict__ prev,
    const float* __restrict__ mask, const float* __restrict__ bk)
{
    __shared__ __align__(16) float xb[NBUF][TTILE][DM];   // 32 KB
    __shared__ __align__(16) float s_part[8][8][TTILE];   // 1 KB
    __shared__ float mask_s[NT_SPLIT * TTILE];            // 52
    __shared__ float sb_s[8];

    const int tid = threadIdx.x;
    const int b = blockIdx.x;
    const int s = blockIdx.y;
    const int w = tid >> 5, lane = tid & 31;
    const int h = lane >> 2, g = lane & 3;

    const float* prevb = prev + (long)b * HIST * 512;
    const float* curb  = cur  + (long)b * 512;

    if (tid < NT_SPLIT * TTILE)
        mask_s[tid] = (tid < T_PER_SPLIT)
            ? mask[b * TT + s * T_PER_SPLIT + tid] : -CUDART_INF_F;
    {   // sb[h] = q[b,h,:]·bk[h,:]; warp w handles head w
        float q1 = g_q[b * 512 + w * 64 + lane];
        float q2 = g_q[b * 512 + w * 64 + 32 + lane];
        float sv = q1 * bk[w * 64 + lane] + q2 * bk[w * 64 + 32 + lane];
#pragma unroll
        for (int o = 16; o; o >>= 1) sv += __shfl_xor_sync(0xffffffffu, sv, o);
        if (lane == 0) sb_s[w] = sv;
    }

    // r fragment: 4 strided float4 chunks (matches x-access mapping)
    u64 rf[8];
    {
        const float* rp = &g_r[(long)b * 4096 + h * 512 + w * 64 + g * 4];
#pragma unroll
        for (int c = 0; c < 4; c++) {
            ulonglong2 v = *(const ulonglong2*)(rp + 16 * c);
            rf[2 * c + 0] = v.x;
            rf[2 * c + 1] = v.y;
        }
    }
    u64 acc[8];
#pragma unroll
    for (int i = 0; i < 8; i++) acc[i] = 0ull;
    float m = -CUDART_INF_F, l = 0.f;

    // prime 3 tiles
#pragma unroll
    for (int i = 0; i < 3; i++) {
        prefetch_tile_s(&xb[i][0][0], prevb, curb, s, i, tid);
        cp_commit();
    }
    __syncthreads();                       // sb_s / mask_s visible
    const float sb = sb_s[h];

    for (int tile = 0; tile < NT_SPLIT; tile++) {
        const int buf = tile & (NBUF - 1);
        cp_wait2();
        __syncthreads();

        const float* xbase = &xb[buf][0][w * 64 + g * 4];
        // ---- partial scores ----
#pragma unroll
        for (int t = 0; t < TTILE; t++) {
            const float* xr = xbase + t * DM;
            ulonglong2 x0 = *(const ulonglong2*)(xr);
            ulonglong2 x1 = *(const ulonglong2*)(xr + 16);
            ulonglong2 x2 = *(const ulonglong2*)(xr + 32);
            ulonglong2 x3 = *(const ulonglong2*)(xr + 48);
            u64 sa = 0ull, sc = 0ull;
            ffma2(sa, rf[0], x0.x); ffma2(sc, rf[1], x0.y);
            ffma2(sa, rf[2], x1.x); ffma2(sc, rf[3], x1.y);
            ffma2(sa, rf[4], x2.x); ffma2(sc, rf[5], x2.y);
            ffma2(sa, rf[6], x3.x); ffma2(sc, rf[7], x3.y);
            float2 fa = unpack2(sa), fc = unpack2(sc);
            float sv = (fa.x + fa.y) + (fc.x + fc.y);
            sv += __shfl_xor_sync(0xffffffffu, sv, 1);
            sv += __shfl_xor_sync(0xffffffffu, sv, 2);
            if (g == 0) s_part[w][h][t] = sv;
        }
        __syncthreads();                   // s_part complete

        if (tile + 3 < NT_SPLIT)
            prefetch_tile_s(&xb[(tile + 3) & (NBUF - 1)][0][0], prevb, curb, s, tile + 3, tid);
        cp_commit();                       // uniform group count

        // ---- per-lane replicated online softmax for head h ----
        float4 a0 = make_float4(0.f, 0.f, 0.f, 0.f);
#pragma unroll
        for (int w2 = 0; w2 < 8; w2++) {
            float4 v = *(const float4*)&s_part[w2][h][0];
            a0.x += v.x; a0.y += v.y; a0.z += v.z; a0.w += v.w;
        }
        const float* mk = &mask_s[tile * TTILE];
        float lg0 = (a0.x + sb) * 0.125f + mk[0];
        float lg1 = (a0.y + sb) * 0.125f + mk[1];
        float lg2 = (a0.z + sb) * 0.125f + mk[2];
        float lg3 = (a0.w + sb) * 0.125f + mk[3];
        float mx = fmaxf(fmaxf(lg0, lg1), fmaxf(lg2, lg3));
        float m_new = fmaxf(m, mx);
        float p[TTILE];
        p[0] = __expf(lg0 - m_new); p[1] = __expf(lg1 - m_new);
        p[2] = __expf(lg2 - m_new); p[3] = __expf(lg3 - m_new);
        float ps = (p[0] + p[1]) + (p[2] + p[3]);
        float scl = __expf(m - m_new);
        l = l * scl + ps;
        m = m_new;

        // ---- rescale + accumulate weighted x ----
        u64 sclp = pack2(scl, scl);
#pragma unroll
        for (int i = 0; i < 8; i++) fmul2(acc[i], sclp);
#pragma unroll
        for (int t = 0; t < TTILE; t++) {
            const float* xr = xbase + t * DM;
            ulonglong2 x0 = *(const ulonglong2*)(xr);
            ulonglong2 x1 = *(const ulonglong2*)(xr + 16);
            ulonglong2 x2 = *(const ulonglong2*)(xr + 32);
            ulonglong2 x3 = *(const ulonglong2*)(xr + 48);
            u64 pv = pack2(p[t], p[t]);
            ffma2(acc[0], pv, x0.x); ffma2(acc[1], pv, x0.y);
            ffma2(acc[2], pv, x1.x); ffma2(acc[3], pv, x1.y);
            ffma2(acc[4], pv, x2.x); ffma2(acc[5], pv, x2.y);
            ffma2(acc[6], pv, x3.x); ffma2(acc[7], pv, x3.y);
        }
    }

    // ---- write UNNORMALIZED partial + (m, l) ----
    float* cpo = &g_pc[((long)(b * TSPLIT + s) * 8 + h) * 512 + w * 64 + g * 4];
#pragma unroll
    for (int c = 0; c < 4; c++) {
        float2 v0 = unpack2(acc[2 * c + 0]);
        float2 v1 = unpack2(acc[2 * c + 1]);
        float4 o = make_float4(v0.x, v0.y, v1.x, v1.y);
        *(float4*)(cpo + 16 * c) = o;
    }
    if (w == 0 && g == 0) {                 // lanes h=0..7, one per head
        g_pml[(b * TSPLIT + s) * 16 + h]     = m;
        g_pml[(b * TSPLIT + s) * 16 + 8 + h] = l;
    }
}

// ============================================================================
// Kernel M: merge 4 split partials -> g_c.  grid 1024, block 256.
// c[b,h,:] = sum_s exp(m_s - M) * acc_s[:] / sum_s exp(m_s - M) * l_s
// ============================================================================
__global__ void __launch_bounds__(256) k_merge()
{
    __shared__ float wol[TSPLIT][8];
    const int tid = threadIdx.x;
    const int b = blockIdx.x;

    if (tid < 32) {
        int s = tid >> 3, h = tid & 7;
        float m = g_pml[(b * TSPLIT + s) * 16 + h];
        float l = g_pml[(b * TSPLIT + s) * 16 + 8 + h];
        float M = m;
        M = fmaxf(M, __shfl_xor_sync(0xffffffffu, M, 8));
        M = fmaxf(M, __shfl_xor_sync(0xffffffffu, M, 16));
        float wgt = __expf(m - M);
        float wl = wgt * l;
        wl += __shfl_xor_sync(0xffffffffu, wl, 8);
        wl += __shfl_xor_sync(0xffffffffu, wl, 16);
        wol[s][h] = wgt / wl;
    }
    __syncthreads();

#pragma unroll
    for (int c = 0; c < 4; c++) {
        int j = c * 1024 + tid * 4;
        int h = j >> 9;
        float4 a = make_float4(0.f, 0.f, 0.f, 0.f);
#pragma unroll
        for (int s = 0; s < TSPLIT; s++) {
            float4 v = *(const float4*)&g_pc[((long)(b * TSPLIT + s)) * 4096 + j];
            float wv = wol[s][h];
            a.x += wv * v.x; a.y += wv * v.y;
            a.z += wv * v.z; a.w += wv * v.w;
        }
        *(float4*)&g_c[(long)b * 4096 + j] = a;
    }
}

// ============================================================================
extern "C" void kernel_launch(void* const* d_in, const int* in_sizes, int n_in,
                              void* d_out, int out_size)
{
    const float* cur  = (const float*)d_in[0];   // [1024, 512]
    const float* prev = (const float*)d_in[1];   // [1024, 199, 512]
    const float* mask = (const float*)d_in[2];   // [1024, 200]
    const float* Wq   = (const float*)d_in[3];   // [512, 512]
    const float* bq   = (const float*)d_in[4];   // [512]
    const float* Wk   = (const float*)d_in[5];   // [512, 512]
    const float* bk   = (const float*)d_in[6];   // [512]
    const float* Wv   = (const float*)d_in[7];   // [512, 512]
    const float* bv   = (const float*)d_in[8];   // [512]
    float* out = (float*)d_out;                  // [1024, 512]

    // q = cur @ Wq^T + bq          (writes g_q internally)
    k_gemm64<true ><<<dim3(32, 8), 256>>>(cur, Wq, bq, nullptr);
    // r[b,h,:] = Wk_h^T q_h        (g_q -> g_r)
    k_rproj<<<dim3(4, 32, 8), 256>>>(Wk);
    // split-T streaming attention  (-> g_pc, g_pml)
    k_attn <<<dim3(1024, TSPLIT), 256>>>(cur, prev, mask, bk);
    // merge partials               (-> g_c)
    k_merge<<<1024, 256>>>();
    // out = c @ Wv_h^T + bv        (reads g_c internally)
    k_gemm64<false><<<dim3(32, 8), 256>>>(nullptr, Wv, bv, out);
}